// round 2
// baseline (speedup 1.0000x reference)
#include <cuda_runtime.h>

// Closed-form evaluation of the 20-qubit, depth-2 circuit.
//
// feature_q = -<Z_q>,
// <Z_q> = c2_q*(c1_q*cx_q) - s2_q*s1_q*cx_q * (c1_{q-1}*cx_{q-1}) * (c1_{q+1}*cx_{q+1})
// boundary neighbor factors = 1; final CZ layer commutes with Z_q.
// logits = feature @ W^T + b.
//
// Layout: blockIdx.x = batch element (32), lane = qubit (lanes 20..31 idle-neutral).
// Neighbor products via warp shuffle; logits via shfl_xor butterfly reduction.

#define N_QUBITS 20

__global__ void quantum_classifier_warp(
    const float* __restrict__ x,      // (32, 20)
    const float* __restrict__ theta,  // (2, 20)
    const float* __restrict__ W,      // (2, 20)
    const float* __restrict__ b,      // (2,)
    float* __restrict__ out)          // (32, 2)
{
    const int w = blockIdx.x;    // batch element
    const int l = threadIdx.x;   // lane = qubit
    const bool active = (l < N_QUBITS);

    // Issue all loads up front (independent, overlap latency).
    float th1 = active ? theta[l]              : 0.0f;
    float th2 = active ? theta[N_QUBITS + l]   : 0.0f;
    float xv  = active ? x[w * N_QUBITS + l]   : 0.0f;
    float w0  = active ? W[l]                  : 0.0f;
    float w1  = active ? W[N_QUBITS + l]       : 0.0f;
    float b0  = b[0];
    float b1  = b[1];

    float s1, c1, s2, c2;
    __sincosf(th1, &s1, &c1);
    __sincosf(th2, &s2, &c2);
    float cx = __cosf(xv);       // inactive lanes: cos(0)=1

    float g = c1 * cx;           // inactive lanes: g = 1 (neutral boundary)

    float left  = __shfl_up_sync(0xffffffffu, g, 1);
    if (l == 0) left = 1.0f;                              // no left neighbor
    float right = __shfl_down_sync(0xffffffffu, g, 1);    // lane 19 pulls lane 20's g == 1

    float z = c2 * g - s2 * s1 * cx * left * right;
    float f = -z;                // feature_q = -<Z_q>; inactive lanes have W=0

    float a0 = f * w0;
    float a1 = f * w1;
#pragma unroll
    for (int off = 16; off > 0; off >>= 1) {
        a0 += __shfl_xor_sync(0xffffffffu, a0, off);
        a1 += __shfl_xor_sync(0xffffffffu, a1, off);
    }

    if (l == 0) {
        float2 r = make_float2(a0 + b0, a1 + b1);
        *reinterpret_cast<float2*>(out + w * 2) = r;
    }
}

extern "C" void kernel_launch(void* const* d_in, const int* in_sizes, int n_in,
                              void* d_out, int out_size) {
    const float* x     = (const float*)d_in[0];  // (32, 20)
    const float* theta = (const float*)d_in[1];  // (2, 20)
    const float* W     = (const float*)d_in[2];  // (2, 20)
    const float* b     = (const float*)d_in[3];  // (2,)
    float* out = (float*)d_out;                  // (32, 2)

    quantum_classifier_warp<<<32, 32>>>(x, theta, W, b, out);
}

// round 4
// speedup vs baseline: 1.4931x; 1.4931x over previous
#include <cuda_runtime.h>

// Closed-form evaluation of the 20-qubit, depth-2 circuit.
//
// feature_q = -<Z_q>,
// <Z_q> = c2_q*(c1_q*cx_q) - s2_q*s1_q*cx_q * (c1_{q-1}*cx_{q-1}) * (c1_{q+1}*cx_{q+1})
// boundary neighbor factors = 1; final CZ layer commutes with Z_q (no marginal effect).
// logits = feature @ W^T + b.
//
// blockIdx.x = batch element (32), lane = qubit (lanes 20..31 neutral).
// Neighbor products via warp shuffle; logits via 5-level shfl_xor butterfly
// (sm_103a has no redux.sync.add.f32 — integer REDUX only).

#define N_QUBITS 20

__global__ void __launch_bounds__(32, 1) quantum_classifier_warp(
    const float* __restrict__ x,      // (32, 20)
    const float* __restrict__ theta,  // (2, 20)
    const float* __restrict__ W,      // (2, 20)
    const float* __restrict__ b,      // (2,)
    float* __restrict__ out)          // (32, 2)
{
    const int w = blockIdx.x;    // batch element
    const int l = threadIdx.x;   // lane = qubit
    const bool active = (l < N_QUBITS);

    // Independent loads issued up front (overlapping latency).
    float th1 = active ? theta[l]            : 0.0f;
    float th2 = active ? theta[N_QUBITS + l] : 0.0f;
    float xv  = active ? x[w * N_QUBITS + l] : 0.0f;
    float w0  = active ? W[l]                : 0.0f;
    float w1  = active ? W[N_QUBITS + l]     : 0.0f;
    float b0 = 0.0f, b1 = 0.0f;
    if (l == 0) { b0 = b[0]; b1 = b[1]; }

    float s1, c1, s2, c2;
    __sincosf(th1, &s1, &c1);
    __sincosf(th2, &s2, &c2);
    float cx = __cosf(xv);       // inactive lanes: cos(0) = 1

    float g = c1 * cx;           // inactive lanes: g = 1 (neutral boundary)

    float left  = __shfl_up_sync(0xffffffffu, g, 1);
    if (l == 0) left = 1.0f;                              // no left neighbor
    float right = __shfl_down_sync(0xffffffffu, g, 1);    // lane 19 reads lane 20's g == 1

    float z = c2 * g - s2 * s1 * cx * left * right;
    float f = -z;                // feature_q = -<Z_q>; inactive lanes carry W = 0

    // Two independent butterfly chains — pipeline through the shuffle unit.
    float a0 = f * w0;
    float a1 = f * w1;
#pragma unroll
    for (int off = 16; off > 0; off >>= 1) {
        a0 += __shfl_xor_sync(0xffffffffu, a0, off);
        a1 += __shfl_xor_sync(0xffffffffu, a1, off);
    }

    if (l == 0) {
        float2 r = make_float2(a0 + b0, a1 + b1);
        *reinterpret_cast<float2*>(out + w * 2) = r;
    }
}

extern "C" void kernel_launch(void* const* d_in, const int* in_sizes, int n_in,
                              void* d_out, int out_size) {
    const float* x     = (const float*)d_in[0];  // (32, 20)
    const float* theta = (const float*)d_in[1];  // (2, 20)
    const float* W     = (const float*)d_in[2];  // (2, 20)
    const float* b     = (const float*)d_in[3];  // (2,)
    float* out = (float*)d_out;                  // (32, 2)

    quantum_classifier_warp<<<32, 32>>>(x, theta, W, b, out);
}